// round 1
// baseline (speedup 1.0000x reference)
#include <cuda_runtime.h>
#include <cstdint>

typedef unsigned long long u64;

// ---- problem constants ----
#define NB      2
#define TF      16
#define SS      256
#define DM      1024
#define ROWS    (NB*TF*SS)        // 8192
#define QKVC    (3*DM)            // 3072
#define HEADS   8
#define DH      64
#define ATT_SCALE 0.125f          // (1024/16)^-0.5

// ---- scratch (device globals: allocation-free rule) ----
__device__ float g_qkv[(size_t)ROWS * QKVC];   // 96 MB
__device__ float g_cat[(size_t)ROWS * DM];     // 32 MB

union F2u { u64 u; float2 f; };

__device__ __forceinline__ u64 ffma2(u64 a, u64 b, u64 c) {
    u64 d;
    asm("fma.rn.f32x2 %0, %1, %2, %3;" : "=l"(d) : "l"(a), "l"(b), "l"(c));
    return d;
}
__device__ __forceinline__ u64 pack2(float x) {
    u64 d;
    asm("mov.b64 %0, {%1, %2};" : "=l"(d) : "f"(x), "f"(x));
    return d;
}

// ============================================================================
// SGEMM: C[M,N] = A[M,K] @ B[K,N] (+bias), fp32 with packed f32x2 FFMA2.
// 128x128 tile, BK=8, 256 threads, 8x8 per thread (as 8x4 f32x2 pairs),
// double-buffered SMEM. M,N,K assumed multiples of tile dims (true here).
// ============================================================================
__global__ void __launch_bounds__(256, 2) sgemm_f32x2(
    const float* __restrict__ A, const float* __restrict__ B,
    float* __restrict__ C, const float* __restrict__ bias,
    int M, int N, int K)
{
    constexpr int BM = 128, BN = 128, BK = 8;
    __shared__ __align__(16) float As[2][BK][BM];
    __shared__ __align__(16) float Bs[2][BK][BN];

    const int tid = threadIdx.x;
    const int tx = tid & 15;          // 0..15 -> 8 cols each
    const int ty = tid >> 4;          // 0..15 -> 8 rows each
    const int bm = blockIdx.y * BM;
    const int bn = blockIdx.x * BN;

    const int aRow = tid >> 1;            // 0..127
    const int aCol = (tid & 1) << 2;      // 0 or 4
    const int bRow = tid >> 5;            // 0..7
    const int bCol = (tid & 31) << 2;     // 0..124

    const float* Aptr = A + (size_t)(bm + aRow) * K + aCol;
    const float* Bptr = B + (size_t)bRow * N + bn + bCol;

    // prologue: tile 0
    float4 a4 = *(const float4*)Aptr;
    float4 b4 = *(const float4*)Bptr;
    As[0][aCol+0][aRow] = a4.x; As[0][aCol+1][aRow] = a4.y;
    As[0][aCol+2][aRow] = a4.z; As[0][aCol+3][aRow] = a4.w;
    *(float4*)&Bs[0][bRow][bCol] = b4;
    __syncthreads();

    u64 acc[8][4];
    #pragma unroll
    for (int i = 0; i < 8; ++i)
        #pragma unroll
        for (int j = 0; j < 4; ++j) acc[i][j] = 0ull;

    const int nT = K / BK;
    int buf = 0;
    for (int t = 0; t < nT; ++t) {
        if (t + 1 < nT) {
            a4 = *(const float4*)(Aptr + (size_t)(t+1)*BK);
            b4 = *(const float4*)(Bptr + (size_t)(t+1)*BK*N);
        }
        #pragma unroll
        for (int kk = 0; kk < BK; ++kk) {
            float4 alo = *(const float4*)&As[buf][kk][ty*8];
            float4 ahi = *(const float4*)&As[buf][kk][ty*8+4];
            u64 ar[8];
            ar[0]=pack2(alo.x); ar[1]=pack2(alo.y); ar[2]=pack2(alo.z); ar[3]=pack2(alo.w);
            ar[4]=pack2(ahi.x); ar[5]=pack2(ahi.y); ar[6]=pack2(ahi.z); ar[7]=pack2(ahi.w);
            const u64* b2p = (const u64*)&Bs[buf][kk][tx*8];
            u64 br0 = b2p[0], br1 = b2p[1], br2 = b2p[2], br3 = b2p[3];
            #pragma unroll
            for (int i = 0; i < 8; ++i) {
                acc[i][0] = ffma2(ar[i], br0, acc[i][0]);
                acc[i][1] = ffma2(ar[i], br1, acc[i][1]);
                acc[i][2] = ffma2(ar[i], br2, acc[i][2]);
                acc[i][3] = ffma2(ar[i], br3, acc[i][3]);
            }
        }
        if (t + 1 < nT) {
            As[buf^1][aCol+0][aRow] = a4.x; As[buf^1][aCol+1][aRow] = a4.y;
            As[buf^1][aCol+2][aRow] = a4.z; As[buf^1][aCol+3][aRow] = a4.w;
            *(float4*)&Bs[buf^1][bRow][bCol] = b4;
            __syncthreads();
            buf ^= 1;
        }
    }

    const int colBase = bn + tx*8;
    #pragma unroll
    for (int i = 0; i < 8; ++i) {
        float* crow = C + (size_t)(bm + ty*8 + i) * N + colBase;
        #pragma unroll
        for (int j = 0; j < 4; ++j) {
            F2u v; v.u = acc[i][j];
            if (bias) {
                v.f.x += bias[colBase + 2*j];
                v.f.y += bias[colBase + 2*j + 1];
            }
            *(float2*)(crow + 2*j) = v.f;
        }
    }
}

// ============================================================================
// Spatial attention: one CTA per (n*T frame, head). K/V tiles (256x64 fp32
// each) resident in SMEM; one query per thread; branchy online softmax.
// qkv layout row stride 3072: q_s @0, k_s @1024, v_s @2048 (+ h*64).
// Writes x_s into g_cat[..., 0:512].
// ============================================================================
__global__ void spatial_attn(const float* __restrict__ qkv, float* __restrict__ cat)
{
    extern __shared__ __align__(16) float sm[];
    float* Ks = sm;                 // [256][64]
    float* Vs = sm + SS*DH;         // [256][64]

    const int b  = blockIdx.x;      // nt*8 + h
    const int h  = b & 7;
    const int nt = b >> 3;
    const float* base = qkv + (size_t)nt * SS * QKVC;
    const int tid = threadIdx.x;    // 256 threads

    #pragma unroll
    for (int i = 0; i < 16; ++i) {
        int f4 = i*256 + tid;
        int k  = f4 >> 4;
        int d4 = (f4 & 15) << 2;
        const float* src = base + (size_t)k*QKVC + h*DH + d4;
        *(float4*)(Ks + k*DH + d4) = *(const float4*)(src + 1024);
        *(float4*)(Vs + k*DH + d4) = *(const float4*)(src + 2048);
    }
    __syncthreads();

    float qr[DH], o[DH];
    const float* qp = base + (size_t)tid*QKVC + h*DH;   // q_s
    #pragma unroll
    for (int d = 0; d < DH; d += 4) {
        float4 v = *(const float4*)(qp + d);
        qr[d]=v.x*ATT_SCALE; qr[d+1]=v.y*ATT_SCALE; qr[d+2]=v.z*ATT_SCALE; qr[d+3]=v.w*ATT_SCALE;
        o[d]=0.f; o[d+1]=0.f; o[d+2]=0.f; o[d+3]=0.f;
    }

    float m = -3.4e38f, l = 0.f;
    for (int j = 0; j < SS; ++j) {
        const float* kj = Ks + j*DH;
        float s0=0.f,s1=0.f,s2=0.f,s3=0.f;
        #pragma unroll
        for (int d = 0; d < DH; d += 4) {
            float4 kv = *(const float4*)(kj + d);
            s0 += qr[d]*kv.x; s1 += qr[d+1]*kv.y; s2 += qr[d+2]*kv.z; s3 += qr[d+3]*kv.w;
        }
        float s = (s0+s1)+(s2+s3);
        const float* vj = Vs + j*DH;
        if (s <= m) {
            float p = __expf(s - m);
            l += p;
            #pragma unroll
            for (int d = 0; d < DH; d += 4) {
                float4 vv = *(const float4*)(vj + d);
                o[d]+=p*vv.x; o[d+1]+=p*vv.y; o[d+2]+=p*vv.z; o[d+3]+=p*vv.w;
            }
        } else {
            float corr = __expf(m - s);      // exp(-huge)=0 on first key
            l = l*corr + 1.f;
            #pragma unroll
            for (int d = 0; d < DH; d += 4) {
                float4 vv = *(const float4*)(vj + d);
                o[d]=o[d]*corr+vv.x; o[d+1]=o[d+1]*corr+vv.y;
                o[d+2]=o[d+2]*corr+vv.z; o[d+3]=o[d+3]*corr+vv.w;
            }
            m = s;
        }
    }
    const float inv = 1.f / l;
    float* op = cat + (size_t)(nt*SS + tid)*DM + h*DH;
    #pragma unroll
    for (int d = 0; d < DH; d += 4) {
        float4 w;
        w.x=o[d]*inv; w.y=o[d+1]*inv; w.z=o[d+2]*inv; w.w=o[d+3]*inv;
        *(float4*)(op + d) = w;
    }
}

// ============================================================================
// Temporal attention: one CTA per (n, spatial s). K_t/V_t tiles [16][512] in
// SMEM; 128 threads = (head, query-t) pairs. k_t @1536, v_t @2560, q_t @512.
// Writes x_t into g_cat[..., 512:1024].
// ============================================================================
__global__ void temporal_attn(const float* __restrict__ qkv, float* __restrict__ cat)
{
    extern __shared__ __align__(16) float sm[];
    float* Ks = sm;                 // [16][512]
    float* Vs = sm + TF*512;

    const int b = blockIdx.x;       // n*256 + s
    const int n = b >> 8;
    const int s = b & 255;
    const int tid = threadIdx.x;    // 128 threads

    #pragma unroll
    for (int i = 0; i < 16; ++i) {
        int f4 = i*128 + tid;
        int t  = f4 >> 7;
        int c4 = (f4 & 127) << 2;
        const float* src = qkv + ((size_t)(n*TF + t)*SS + s)*QKVC + c4;
        *(float4*)(Ks + t*512 + c4) = *(const float4*)(src + 1536);
        *(float4*)(Vs + t*512 + c4) = *(const float4*)(src + 2560);
    }
    __syncthreads();

    const int h  = tid >> 4;
    const int tq = tid & 15;
    float qr[DH], o[DH];
    const float* qp = qkv + ((size_t)(n*TF + tq)*SS + s)*QKVC + 512 + h*DH;  // q_t
    #pragma unroll
    for (int d = 0; d < DH; d += 4) {
        float4 v = *(const float4*)(qp + d);
        qr[d]=v.x*ATT_SCALE; qr[d+1]=v.y*ATT_SCALE; qr[d+2]=v.z*ATT_SCALE; qr[d+3]=v.w*ATT_SCALE;
        o[d]=0.f; o[d+1]=0.f; o[d+2]=0.f; o[d+3]=0.f;
    }

    float m = -3.4e38f, l = 0.f;
    #pragma unroll
    for (int j = 0; j < TF; ++j) {
        const float* kj = Ks + j*512 + h*DH;
        float s0=0.f,s1=0.f,s2=0.f,s3=0.f;
        #pragma unroll
        for (int d = 0; d < DH; d += 4) {
            float4 kv = *(const float4*)(kj + d);
            s0 += qr[d]*kv.x; s1 += qr[d+1]*kv.y; s2 += qr[d+2]*kv.z; s3 += qr[d+3]*kv.w;
        }
        float sl = (s0+s1)+(s2+s3);
        const float* vj = Vs + j*512 + h*DH;
        if (sl <= m) {
            float p = __expf(sl - m);
            l += p;
            #pragma unroll
            for (int d = 0; d < DH; d += 4) {
                float4 vv = *(const float4*)(vj + d);
                o[d]+=p*vv.x; o[d+1]+=p*vv.y; o[d+2]+=p*vv.z; o[d+3]+=p*vv.w;
            }
        } else {
            float corr = __expf(m - sl);
            l = l*corr + 1.f;
            #pragma unroll
            for (int d = 0; d < DH; d += 4) {
                float4 vv = *(const float4*)(vj + d);
                o[d]=o[d]*corr+vv.x; o[d+1]=o[d+1]*corr+vv.y;
                o[d+2]=o[d+2]*corr+vv.z; o[d+3]=o[d+3]*corr+vv.w;
            }
            m = sl;
        }
    }
    const float inv = 1.f / l;
    float* op = cat + ((size_t)(n*TF + tq)*SS + s)*DM + 512 + h*DH;
    #pragma unroll
    for (int d = 0; d < DH; d += 4) {
        float4 w;
        w.x=o[d]*inv; w.y=o[d+1]*inv; w.z=o[d+2]*inv; w.w=o[d+3]*inv;
        *(float4*)(op + d) = w;
    }
}

// ============================================================================
// Launch: qkv GEMM -> spatial attn -> temporal attn -> proj GEMM (+bias).
// All launches on default stream (graph-capturable, allocation-free).
// ============================================================================
extern "C" void kernel_launch(void* const* d_in, const int* in_sizes, int n_in,
                              void* d_out, int out_size)
{
    const float* x     = (const float*)d_in[0];   // [2,16,256,1024]
    const float* Wqkv  = (const float*)d_in[1];   // [1024,3072]
    const float* Wproj = (const float*)d_in[2];   // [1024,1024]
    const float* bproj = (const float*)d_in[3];   // [1024]
    float* out = (float*)d_out;

    float *qkv, *cat;
    cudaGetSymbolAddress((void**)&qkv, g_qkv);
    cudaGetSymbolAddress((void**)&cat, g_cat);

    // 1) qkv = x @ Wqkv   [8192,1024]x[1024,3072]
    {
        dim3 grid(QKVC/128, ROWS/128);
        sgemm_f32x2<<<grid, 256>>>(x, Wqkv, qkv, nullptr, ROWS, QKVC, DM);
    }

    // 2) spatial attention -> cat[:, 0:512]
    {
        int smem = 2 * SS * DH * (int)sizeof(float);   // 128 KB
        cudaFuncSetAttribute(spatial_attn, cudaFuncAttributeMaxDynamicSharedMemorySize, smem);
        spatial_attn<<<NB*TF*HEADS, 256, smem>>>(qkv, cat);
    }

    // 3) temporal attention -> cat[:, 512:1024]
    {
        int smem = 2 * TF * 512 * (int)sizeof(float);  // 64 KB
        cudaFuncSetAttribute(temporal_attn, cudaFuncAttributeMaxDynamicSharedMemorySize, smem);
        temporal_attn<<<NB*SS, 128, smem>>>(qkv, cat);
    }

    // 4) out = cat @ Wproj + bproj   [8192,1024]x[1024,1024]
    {
        dim3 grid(DM/128, ROWS/128);
        sgemm_f32x2<<<grid, 256>>>(cat, Wproj, out, bproj, ROWS, DM, DM);
    }
}

// round 5
// speedup vs baseline: 2.3818x; 2.3818x over previous
#include <cuda_runtime.h>
#include <cstdint>

typedef unsigned long long u64;
typedef unsigned int u32;

// ---- problem constants ----
#define NB      2
#define TF      16
#define SS      256
#define DM      1024
#define ROWS    (NB*TF*SS)        // 8192
#define QKVC    (3*DM)            // 3072
#define HEADS   8
#define DH      64
#define ATT_SCALE 0.125f

// ---- scratch (device globals: allocation-free rule) ----
__device__ float g_qkv[(size_t)ROWS * QKVC];    // 96 MB
__device__ float g_cat[(size_t)ROWS * DM];      // 32 MB
__device__ float g_WqkvT[(size_t)QKVC * DM];    // 12 MB  (Wqkv^T : [3072][1024])
__device__ float g_WprojT[(size_t)DM * DM];     // 4 MB   (Wproj^T: [1024][1024])

// ============================================================================
// PTX helpers (arch-neutral: mma.sync + cvt only, no tcgen05)
// ============================================================================
__device__ __forceinline__ u32 f2tf32(float x) {
    u32 r;
    asm("cvt.rna.tf32.f32 %0, %1;" : "=r"(r) : "f"(x));
    return r;
}
__device__ __forceinline__ void mma16n8k8(float* c, const u32* a, const u32* b) {
    asm volatile(
        "mma.sync.aligned.m16n8k8.row.col.f32.tf32.tf32.f32 "
        "{%0,%1,%2,%3}, {%4,%5,%6,%7}, {%8,%9}, {%0,%1,%2,%3};"
        : "+f"(c[0]), "+f"(c[1]), "+f"(c[2]), "+f"(c[3])
        : "r"(a[0]), "r"(a[1]), "r"(a[2]), "r"(a[3]), "r"(b[0]), "r"(b[1]));
}

// ============================================================================
// Weight transpose: W [K][N] -> WT [N][K]   (runs once per launch, tiny)
// ============================================================================
__global__ void transpose_k(const float* __restrict__ W, float* __restrict__ WT,
                            int K, int N)
{
    __shared__ float tile[32][33];
    const int bx = blockIdx.x * 32;   // N
    const int by = blockIdx.y * 32;   // K
    const int tx = threadIdx.x, ty = threadIdx.y;   // 32 x 8
    #pragma unroll
    for (int i = 0; i < 32; i += 8)
        tile[ty + i][tx] = W[(size_t)(by + ty + i) * N + bx + tx];
    __syncthreads();
    #pragma unroll
    for (int i = 0; i < 32; i += 8)
        WT[(size_t)(bx + ty + i) * K + by + tx] = tile[tx][ty + i];
}

// ============================================================================
// tf32 tensor-core GEMM via mma.sync (legacy HMMA path, compute_103-safe):
//   C[M,N] = A[M,K] @ BT[N,K]^T (+bias)
// 128x128 tile, BK=16, 256 thr = 8 warps, warp tile 64x32 (4x4 m16n8k8).
// SMEM row-major [rows][BK+4]: fragment LDS conflict-free (20*g + tig perm).
// ============================================================================
#define BM 128
#define BN 128
#define BK 16
#define KSTR (BK + 4)     // 20

__global__ void __launch_bounds__(256) gemm_tf32mma(
    const float* __restrict__ A, const float* __restrict__ BT,
    float* __restrict__ C, const float* __restrict__ bias,
    int M, int N, int K)
{
    __shared__ u32 As[2][BM][KSTR];   // 20 KB
    __shared__ u32 Bs[2][BN][KSTR];   // 20 KB

    const int tid = threadIdx.x;
    const int wid = tid >> 5;
    const int lid = tid & 31;
    const int g   = lid >> 2;         // groupID
    const int tig = lid & 3;          // thread-in-group
    const int wm  = (wid >> 2) * 64;  // warp M origin (0,64)
    const int wn  = (wid & 3) * 32;   // warp N origin (0..96)
    const int bm = blockIdx.y * BM;
    const int bn = blockIdx.x * BN;

    // producer mapping: idx -> (row, quad-of-4-floats); coalesced float4 loads
    const int pr = tid >> 2;          // 0..63
    const int pq = tid & 3;           // 0..3

    float acc[4][4][4];
    #pragma unroll
    for (int mt = 0; mt < 4; ++mt)
        #pragma unroll
        for (int nt = 0; nt < 4; ++nt)
            #pragma unroll
            for (int i = 0; i < 4; ++i) acc[mt][nt][i] = 0.f;

    const int NT = K / BK;            // 64
    float4 av[2], bv[2];

    // prologue: tile 0 -> SMEM
    #pragma unroll
    for (int i = 0; i < 2; ++i) {
        int m = i * 64 + pr;
        av[i] = *(const float4*)(A  + (size_t)(bm + m) * K + pq * 4);
        bv[i] = *(const float4*)(BT + (size_t)(bn + m) * K + pq * 4);
    }
    #pragma unroll
    for (int i = 0; i < 2; ++i) {
        int m = i * 64 + pr;
        uint4 ta = make_uint4(f2tf32(av[i].x), f2tf32(av[i].y), f2tf32(av[i].z), f2tf32(av[i].w));
        uint4 tb = make_uint4(f2tf32(bv[i].x), f2tf32(bv[i].y), f2tf32(bv[i].z), f2tf32(bv[i].w));
        *(uint4*)&As[0][m][pq * 4] = ta;
        *(uint4*)&Bs[0][m][pq * 4] = tb;
    }
    __syncthreads();

    for (int t = 0; t < NT; ++t) {
        const int buf = t & 1;
        if (t + 1 < NT) {
            const int k0 = (t + 1) * BK;
            #pragma unroll
            for (int i = 0; i < 2; ++i) {
                int m = i * 64 + pr;
                av[i] = *(const float4*)(A  + (size_t)(bm + m) * K + k0 + pq * 4);
                bv[i] = *(const float4*)(BT + (size_t)(bn + m) * K + k0 + pq * 4);
            }
        }
        // compute on buf
        #pragma unroll
        for (int ks = 0; ks < 2; ++ks) {
            const int kc = ks * 8 + tig;
            u32 af[4][4], bf[4][2];
            #pragma unroll
            for (int mt = 0; mt < 4; ++mt) {
                const int r = wm + mt * 16 + g;
                af[mt][0] = As[buf][r    ][kc];
                af[mt][1] = As[buf][r + 8][kc];
                af[mt][2] = As[buf][r    ][kc + 4];
                af[mt][3] = As[buf][r + 8][kc + 4];
            }
            #pragma unroll
            for (int nt = 0; nt < 4; ++nt) {
                const int n = wn + nt * 8 + g;
                bf[nt][0] = Bs[buf][n][kc];
                bf[nt][1] = Bs[buf][n][kc + 4];
            }
            #pragma unroll
            for (int mt = 0; mt < 4; ++mt)
                #pragma unroll
                for (int nt = 0; nt < 4; ++nt)
                    mma16n8k8(acc[mt][nt], af[mt], bf[nt]);
        }
        if (t + 1 < NT) {
            #pragma unroll
            for (int i = 0; i < 2; ++i) {
                int m = i * 64 + pr;
                uint4 ta = make_uint4(f2tf32(av[i].x), f2tf32(av[i].y), f2tf32(av[i].z), f2tf32(av[i].w));
                uint4 tb = make_uint4(f2tf32(bv[i].x), f2tf32(bv[i].y), f2tf32(bv[i].z), f2tf32(bv[i].w));
                *(uint4*)&As[buf ^ 1][m][pq * 4] = ta;
                *(uint4*)&Bs[buf ^ 1][m][pq * 4] = tb;
            }
            __syncthreads();
        }
    }

    // epilogue: c0,c1 -> (row, 2*tig..+1), c2,c3 -> (row+8, ...)
    #pragma unroll
    for (int mt = 0; mt < 4; ++mt) {
        const int r0 = bm + wm + mt * 16 + g;
        #pragma unroll
        for (int nt = 0; nt < 4; ++nt) {
            const int c0 = bn + wn + nt * 8 + 2 * tig;
            float2 v0, v1;
            v0.x = acc[mt][nt][0]; v0.y = acc[mt][nt][1];
            v1.x = acc[mt][nt][2]; v1.y = acc[mt][nt][3];
            if (bias) {
                float2 b2 = *(const float2*)(bias + c0);
                v0.x += b2.x; v0.y += b2.y;
                v1.x += b2.x; v1.y += b2.y;
            }
            *(float2*)(C + (size_t)r0 * N + c0)       = v0;
            *(float2*)(C + (size_t)(r0 + 8) * N + c0) = v1;
        }
    }
}

// ============================================================================
// Spatial attention (unchanged, measured fast): one CTA per (frame, head).
// ============================================================================
__global__ void spatial_attn(const float* __restrict__ qkv, float* __restrict__ cat)
{
    extern __shared__ __align__(16) float sm[];
    float* Ks = sm;
    float* Vs = sm + SS*DH;

    const int b  = blockIdx.x;
    const int h  = b & 7;
    const int nt = b >> 3;
    const float* base = qkv + (size_t)nt * SS * QKVC;
    const int tid = threadIdx.x;

    #pragma unroll
    for (int i = 0; i < 16; ++i) {
        int f4 = i*256 + tid;
        int k  = f4 >> 4;
        int d4 = (f4 & 15) << 2;
        const float* src = base + (size_t)k*QKVC + h*DH + d4;
        *(float4*)(Ks + k*DH + d4) = *(const float4*)(src + 1024);
        *(float4*)(Vs + k*DH + d4) = *(const float4*)(src + 2048);
    }
    __syncthreads();

    float qr[DH], o[DH];
    const float* qp = base + (size_t)tid*QKVC + h*DH;
    #pragma unroll
    for (int d = 0; d < DH; d += 4) {
        float4 v = *(const float4*)(qp + d);
        qr[d]=v.x*ATT_SCALE; qr[d+1]=v.y*ATT_SCALE; qr[d+2]=v.z*ATT_SCALE; qr[d+3]=v.w*ATT_SCALE;
        o[d]=0.f; o[d+1]=0.f; o[d+2]=0.f; o[d+3]=0.f;
    }

    float m = -3.4e38f, l = 0.f;
    for (int j = 0; j < SS; ++j) {
        const float* kj = Ks + j*DH;
        float s0=0.f,s1=0.f,s2=0.f,s3=0.f;
        #pragma unroll
        for (int d = 0; d < DH; d += 4) {
            float4 kv = *(const float4*)(kj + d);
            s0 += qr[d]*kv.x; s1 += qr[d+1]*kv.y; s2 += qr[d+2]*kv.z; s3 += qr[d+3]*kv.w;
        }
        float s = (s0+s1)+(s2+s3);
        const float* vj = Vs + j*DH;
        if (s <= m) {
            float p = __expf(s - m);
            l += p;
            #pragma unroll
            for (int d = 0; d < DH; d += 4) {
                float4 vv = *(const float4*)(vj + d);
                o[d]+=p*vv.x; o[d+1]+=p*vv.y; o[d+2]+=p*vv.z; o[d+3]+=p*vv.w;
            }
        } else {
            float corr = __expf(m - s);
            l = l*corr + 1.f;
            #pragma unroll
            for (int d = 0; d < DH; d += 4) {
                float4 vv = *(const float4*)(vj + d);
                o[d]=o[d]*corr+vv.x; o[d+1]=o[d+1]*corr+vv.y;
                o[d+2]=o[d+2]*corr+vv.z; o[d+3]=o[d+3]*corr+vv.w;
            }
            m = s;
        }
    }
    const float inv = 1.f / l;
    float* op = cat + (size_t)(nt*SS + tid)*DM + h*DH;
    #pragma unroll
    for (int d = 0; d < DH; d += 4) {
        float4 w;
        w.x=o[d]*inv; w.y=o[d+1]*inv; w.z=o[d+2]*inv; w.w=o[d+3]*inv;
        *(float4*)(op + d) = w;
    }
}

// ============================================================================
// Temporal attention (unchanged): one CTA per (n, spatial s).
// ============================================================================
__global__ void temporal_attn(const float* __restrict__ qkv, float* __restrict__ cat)
{
    extern __shared__ __align__(16) float sm[];
    float* Ks = sm;
    float* Vs = sm + TF*512;

    const int b = blockIdx.x;
    const int n = b >> 8;
    const int s = b & 255;
    const int tid = threadIdx.x;

    #pragma unroll
    for (int i = 0; i < 16; ++i) {
        int f4 = i*128 + tid;
        int t  = f4 >> 7;
        int c4 = (f4 & 127) << 2;
        const float* src = qkv + ((size_t)(n*TF + t)*SS + s)*QKVC + c4;
        *(float4*)(Ks + t*512 + c4) = *(const float4*)(src + 1536);
        *(float4*)(Vs + t*512 + c4) = *(const float4*)(src + 2560);
    }
    __syncthreads();

    const int h  = tid >> 4;
    const int tq = tid & 15;
    float qr[DH], o[DH];
    const float* qp = qkv + ((size_t)(n*TF + tq)*SS + s)*QKVC + 512 + h*DH;
    #pragma unroll
    for (int d = 0; d < DH; d += 4) {
        float4 v = *(const float4*)(qp + d);
        qr[d]=v.x*ATT_SCALE; qr[d+1]=v.y*ATT_SCALE; qr[d+2]=v.z*ATT_SCALE; qr[d+3]=v.w*ATT_SCALE;
        o[d]=0.f; o[d+1]=0.f; o[d+2]=0.f; o[d+3]=0.f;
    }

    float m = -3.4e38f, l = 0.f;
    #pragma unroll
    for (int j = 0; j < TF; ++j) {
        const float* kj = Ks + j*512 + h*DH;
        float s0=0.f,s1=0.f,s2=0.f,s3=0.f;
        #pragma unroll
        for (int d = 0; d < DH; d += 4) {
            float4 kv = *(const float4*)(kj + d);
            s0 += qr[d]*kv.x; s1 += qr[d+1]*kv.y; s2 += qr[d+2]*kv.z; s3 += qr[d+3]*kv.w;
        }
        float sl = (s0+s1)+(s2+s3);
        const float* vj = Vs + j*512 + h*DH;
        if (sl <= m) {
            float p = __expf(sl - m);
            l += p;
            #pragma unroll
            for (int d = 0; d < DH; d += 4) {
                float4 vv = *(const float4*)(vj + d);
                o[d]+=p*vv.x; o[d+1]+=p*vv.y; o[d+2]+=p*vv.z; o[d+3]+=p*vv.w;
            }
        } else {
            float corr = __expf(m - sl);
            l = l*corr + 1.f;
            #pragma unroll
            for (int d = 0; d < DH; d += 4) {
                float4 vv = *(const float4*)(vj + d);
                o[d]=o[d]*corr+vv.x; o[d+1]=o[d+1]*corr+vv.y;
                o[d+2]=o[d+2]*corr+vv.z; o[d+3]=o[d+3]*corr+vv.w;
            }
            m = sl;
        }
    }
    const float inv = 1.f / l;
    float* op = cat + ((size_t)(n*TF + tq)*SS + s)*DM + 512 + h*DH;
    #pragma unroll
    for (int d = 0; d < DH; d += 4) {
        float4 w;
        w.x=o[d]*inv; w.y=o[d+1]*inv; w.z=o[d+2]*inv; w.w=o[d+3]*inv;
        *(float4*)(op + d) = w;
    }
}

// ============================================================================
// Launch
// ============================================================================
extern "C" void kernel_launch(void* const* d_in, const int* in_sizes, int n_in,
                              void* d_out, int out_size)
{
    const float* x     = (const float*)d_in[0];
    const float* Wqkv  = (const float*)d_in[1];
    const float* Wproj = (const float*)d_in[2];
    const float* bproj = (const float*)d_in[3];
    float* out = (float*)d_out;

    float *qkv, *cat, *WqkvT, *WprojT;
    cudaGetSymbolAddress((void**)&qkv,    g_qkv);
    cudaGetSymbolAddress((void**)&cat,    g_cat);
    cudaGetSymbolAddress((void**)&WqkvT,  g_WqkvT);
    cudaGetSymbolAddress((void**)&WprojT, g_WprojT);

    // 0) transpose weights to [N][K]
    {
        dim3 blk(32, 8);
        transpose_k<<<dim3(QKVC/32, DM/32), blk>>>(Wqkv, WqkvT, DM, QKVC);
        transpose_k<<<dim3(DM/32, DM/32), blk>>>(Wproj, WprojT, DM, DM);
    }

    // 1) qkv = x @ Wqkv   (tf32 mma.sync)
    {
        dim3 grid(QKVC/BN, ROWS/BM);   // 24 x 64
        gemm_tf32mma<<<grid, 256>>>(x, WqkvT, qkv, nullptr, ROWS, QKVC, DM);
    }

    // 2) spatial attention -> cat[:, 0:512]
    {
        int smem = 2 * SS * DH * (int)sizeof(float);
        cudaFuncSetAttribute(spatial_attn, cudaFuncAttributeMaxDynamicSharedMemorySize, smem);
        spatial_attn<<<NB*TF*HEADS, 256, smem>>>(qkv, cat);
    }

    // 3) temporal attention -> cat[:, 512:1024]
    {
        int smem = 2 * TF * 512 * (int)sizeof(float);
        cudaFuncSetAttribute(temporal_attn, cudaFuncAttributeMaxDynamicSharedMemorySize, smem);
        temporal_attn<<<NB*SS, 128, smem>>>(qkv, cat);
    }

    // 4) out = cat @ Wproj + bproj   (tf32 mma.sync)
    {
        dim3 grid(DM/BN, ROWS/BM);     // 8 x 64
        gemm_tf32mma<<<grid, 256>>>(cat, WprojT, out, bproj, ROWS, DM, DM);
    }
}

// round 6
// speedup vs baseline: 2.4446x; 1.0264x over previous
#include <cuda_runtime.h>
#include <cstdint>

typedef unsigned long long u64;
typedef unsigned int u32;

// ---- problem constants ----
#define NB      2
#define TF      16
#define SS      256
#define DM      1024
#define ROWS    (NB*TF*SS)        // 8192
#define QKVC    (3*DM)            // 3072
#define HEADS   8
#define DH      64
#define ATT_SCALE 0.125f
#define QSCALE_LOG2 0.18033688f   // ATT_SCALE * log2(e)
#define SOFT_OFF 4.0f             // constant offset in log2 domain (cancels in softmax)

// ---- scratch (device globals: allocation-free rule) ----
__device__ float g_qkv[(size_t)ROWS * QKVC];    // 96 MB
__device__ float g_cat[(size_t)ROWS * DM];      // 32 MB (stages x_tf32, then attn output)
__device__ float g_WqkvT[(size_t)QKVC * DM];    // 12 MB  (Wqkv^T, tf32 bits)
__device__ float g_WprojT[(size_t)DM * DM];     // 4 MB   (Wproj^T, tf32 bits)

// ============================================================================
// PTX helpers (arch-neutral: mma.sync / cp.async / cvt — no tcgen05)
// ============================================================================
__device__ __forceinline__ u32 f2tf32(float x) {
    u32 r;
    asm("cvt.rna.tf32.f32 %0, %1;" : "=r"(r) : "f"(x));
    return r;
}
__device__ __forceinline__ float tf32r(float x) { return __uint_as_float(f2tf32(x)); }

__device__ __forceinline__ void mma16n8k8(float* c, const u32* a, const u32* b) {
    asm volatile(
        "mma.sync.aligned.m16n8k8.row.col.f32.tf32.tf32.f32 "
        "{%0,%1,%2,%3}, {%4,%5,%6,%7}, {%8,%9}, {%0,%1,%2,%3};"
        : "+f"(c[0]), "+f"(c[1]), "+f"(c[2]), "+f"(c[3])
        : "r"(a[0]), "r"(a[1]), "r"(a[2]), "r"(a[3]), "r"(b[0]), "r"(b[1]));
}
__device__ __forceinline__ u32 smem_u32(const void* p) {
    u32 a;
    asm("{ .reg .u64 t; cvta.to.shared.u64 t, %1; cvt.u32.u64 %0, t; }" : "=r"(a) : "l"(p));
    return a;
}
__device__ __forceinline__ void cp_async16(u32 dst, const void* src) {
    asm volatile("cp.async.ca.shared.global [%0], [%1], 16;" :: "r"(dst), "l"(src) : "memory");
}
__device__ __forceinline__ u64 ffma2(u64 a, u64 b, u64 c) {
    u64 d;
    asm("fma.rn.f32x2 %0, %1, %2, %3;" : "=l"(d) : "l"(a), "l"(b), "l"(c));
    return d;
}
__device__ __forceinline__ u64 pack2(float x) {
    u64 d;
    asm("mov.b64 %0, {%1, %2};" : "=l"(d) : "f"(x), "f"(x));
    return d;
}
__device__ __forceinline__ void unpack2(u64 v, float& lo, float& hi) {
    asm("mov.b64 {%0, %1}, %2;" : "=f"(lo), "=f"(hi) : "l"(v));
}
// 2^t via magic-number split + deg-4 poly. FMA-pipe only, no MUFU. |t| < 30.
__device__ __forceinline__ float exp2_fast(float t) {
    float z = t + 12582912.0f;           // 1.5*2^23: mantissa holds round(t)
    float n = z - 12582912.0f;
    float f = t - n;                     // f in [-0.5, 0.5]
    float p = 9.6180e-3f;
    p = fmaf(p, f, 5.55041e-2f);
    p = fmaf(p, f, 2.4022650e-1f);
    p = fmaf(p, f, 6.9314718e-1f);
    p = fmaf(p, f, 1.0f);
    return __int_as_float(__float_as_int(p) + (__float_as_int(z) << 23));
}

// ============================================================================
// x -> tf32 rounded copy (for conversion-free GEMM A loads)
// ============================================================================
__global__ void cvt_tf32_vec(const float4* __restrict__ in, float4* __restrict__ out, int n4)
{
    int i = blockIdx.x * blockDim.x + threadIdx.x;
    if (i < n4) {
        float4 v = in[i];
        v.x = tf32r(v.x); v.y = tf32r(v.y); v.z = tf32r(v.z); v.w = tf32r(v.w);
        out[i] = v;
    }
}

// ============================================================================
// Weight transpose + tf32 convert: W [K][N] -> WT [N][K] (tf32 bits)
// ============================================================================
__global__ void transpose_k(const float* __restrict__ W, float* __restrict__ WT,
                            int K, int N)
{
    __shared__ float tile[32][33];
    const int bx = blockIdx.x * 32;   // N
    const int by = blockIdx.y * 32;   // K
    const int tx = threadIdx.x, ty = threadIdx.y;   // 32 x 8
    #pragma unroll
    for (int i = 0; i < 32; i += 8)
        tile[ty + i][tx] = W[(size_t)(by + ty + i) * N + bx + tx];
    __syncthreads();
    #pragma unroll
    for (int i = 0; i < 32; i += 8)
        WT[(size_t)(bx + ty + i) * K + by + tx] = tf32r(tile[tx][ty + i]);
}

// ============================================================================
// tf32 mma.sync GEMM, cp.async 3-stage pipeline, tile 256x128xK (BK=16).
// Operands already tf32-rounded in gmem (no in-loop cvt).
// 256 thr = 8 warps as 4x2 of 64x64 warp tiles. acc 4x8 m16n8k8 per warp.
// ============================================================================
#define BM 256
#define BN 128
#define BK 16
#define KSTR (BK + 4)     // 20
#define STG 3
#define GEMM_SMEM (STG*(BM+BN)*KSTR*4)   // 92160 B

__global__ void __launch_bounds__(256, 1) gemm_tf32mma(
    const float* __restrict__ A, const float* __restrict__ BT,
    float* __restrict__ C, const float* __restrict__ bias,
    int M, int N, int K)
{
    extern __shared__ __align__(16) u32 dsm[];
    u32* As = dsm;                         // [STG][BM][KSTR]
    u32* Bs = dsm + STG * BM * KSTR;       // [STG][BN][KSTR]

    const int tid = threadIdx.x;
    const int wid = tid >> 5;
    const int lid = tid & 31;
    const int g   = lid >> 2;
    const int tig = lid & 3;
    const int wm  = (wid >> 1) * 64;       // 0,64,128,192
    const int wn  = (wid & 1) * 64;        // 0,64
    const int bm = blockIdx.y * BM;
    const int bn = blockIdx.x * BN;
    const int pr = tid >> 2;               // 0..63
    const int pq = (tid & 3) * 4;          // float offset 0,4,8,12

    const int NT = K / BK;

    // stage issue: A 4 rows + B 2 rows per thread, 16B cp.async each
    #define ISSUE_STAGE(t) do {                                              \
        int st_ = (t) % STG; int k0_ = (t) * BK;                             \
        _Pragma("unroll")                                                    \
        for (int i_ = 0; i_ < 4; ++i_) {                                     \
            int m_ = i_ * 64 + pr;                                           \
            cp_async16(smem_u32(&As[(st_*BM + m_)*KSTR + pq]),               \
                       A + (size_t)(bm + m_) * K + k0_ + pq);                \
        }                                                                    \
        _Pragma("unroll")                                                    \
        for (int i_ = 0; i_ < 2; ++i_) {                                     \
            int m_ = i_ * 64 + pr;                                           \
            cp_async16(smem_u32(&Bs[(st_*BN + m_)*KSTR + pq]),               \
                       BT + (size_t)(bn + m_) * K + k0_ + pq);               \
        }                                                                    \
        asm volatile("cp.async.commit_group;" ::: "memory");                 \
    } while (0)

    ISSUE_STAGE(0);
    ISSUE_STAGE(1);

    float acc[4][8][4];
    #pragma unroll
    for (int mt = 0; mt < 4; ++mt)
        #pragma unroll
        for (int nt = 0; nt < 8; ++nt)
            #pragma unroll
            for (int i = 0; i < 4; ++i) acc[mt][nt][i] = 0.f;

    for (int t = 0; t < NT; ++t) {
        if (t < NT - 2) asm volatile("cp.async.wait_group 1;" ::: "memory");
        else            asm volatile("cp.async.wait_group 0;" ::: "memory");
        __syncthreads();
        if (t + 2 < NT) ISSUE_STAGE(t + 2);

        const int st = t % STG;
        #pragma unroll
        for (int ks = 0; ks < 2; ++ks) {
            const int kc = ks * 8 + tig;
            u32 af[4][4], bf[8][2];
            #pragma unroll
            for (int mt = 0; mt < 4; ++mt) {
                const int r = wm + mt * 16 + g;
                af[mt][0] = As[(st*BM + r    )*KSTR + kc];
                af[mt][1] = As[(st*BM + r + 8)*KSTR + kc];
                af[mt][2] = As[(st*BM + r    )*KSTR + kc + 4];
                af[mt][3] = As[(st*BM + r + 8)*KSTR + kc + 4];
            }
            #pragma unroll
            for (int nt = 0; nt < 8; ++nt) {
                const int n = wn + nt * 8 + g;
                bf[nt][0] = Bs[(st*BN + n)*KSTR + kc];
                bf[nt][1] = Bs[(st*BN + n)*KSTR + kc + 4];
            }
            #pragma unroll
            for (int mt = 0; mt < 4; ++mt)
                #pragma unroll
                for (int nt = 0; nt < 8; ++nt)
                    mma16n8k8(acc[mt][nt], af[mt], bf[nt]);
        }
        __syncthreads();
    }

    #pragma unroll
    for (int mt = 0; mt < 4; ++mt) {
        const int r0 = bm + wm + mt * 16 + g;
        #pragma unroll
        for (int nt = 0; nt < 8; ++nt) {
            const int c0 = bn + wn + nt * 8 + 2 * tig;
            float2 v0, v1;
            v0.x = acc[mt][nt][0]; v0.y = acc[mt][nt][1];
            v1.x = acc[mt][nt][2]; v1.y = acc[mt][nt][3];
            if (bias) {
                float2 b2 = *(const float2*)(bias + c0);
                v0.x += b2.x; v0.y += b2.y;
                v1.x += b2.x; v1.y += b2.y;
            }
            *(float2*)(C + (size_t)r0 * N + c0)       = v0;
            *(float2*)(C + (size_t)(r0 + 8) * N + c0) = v1;
        }
    }
}

// ============================================================================
// Spatial attention: one CTA per (frame, head), 512 threads.
// 2 lanes per query (lane^16 partner), 32 dims each. FFMA2 + MUFU-free exp2,
// branch-free softmax via constant offset (cancels in p/sum(p)).
// ============================================================================
__global__ void __launch_bounds__(512) spatial_attn(
    const float* __restrict__ qkv, float* __restrict__ cat)
{
    extern __shared__ __align__(16) char smraw[];
    u64* K2 = (u64*)smraw;              // [256][32] f32x2
    u64* V2 = K2 + SS * 32;
    float4* Kf = (float4*)K2;
    float4* Vf = (float4*)V2;

    const int b  = blockIdx.x;
    const int h  = b & 7;
    const int nt = b >> 3;
    const float* base = qkv + (size_t)nt * SS * QKVC;
    const int tid = threadIdx.x;        // 512

    // load K,V: 8192 float4 total
    #pragma unroll
    for (int i = 0; i < 16; ++i) {
        int idx = i * 512 + tid;
        int which = idx >> 12;          // 0=K, 1=V
        int r = idx & 4095;
        int row = r >> 4;
        int c = r & 15;                 // float4 col
        const float4* src = (const float4*)(base + (size_t)row * QKVC + h * DH
                                            + c * 4 + (which ? 2048 : 1024));
        (which ? Vf : Kf)[row * 16 + c] = *src;
    }
    __syncthreads();

    const int w = tid >> 5;
    const int l = tid & 31;
    const int q = w * 16 + (l & 15);    // query 0..255
    const int half = l >> 4;            // dim half

    // q row, pre-scaled into log2 domain, packed f32x2
    u64 qr2[16], o2[16];
    {
        const float* qp = base + (size_t)q * QKVC + h * DH + half * 32;
        #pragma unroll
        for (int i = 0; i < 8; ++i) {
            float4 v = *(const float4*)(qp + i * 4);
            float2 a, b2;
            a.x = v.x * QSCALE_LOG2; a.y = v.y * QSCALE_LOG2;
            b2.x = v.z * QSCALE_LOG2; b2.y = v.w * QSCALE_LOG2;
            qr2[i*2]   = *(u64*)&a;
            qr2[i*2+1] = *(u64*)&b2;
        }
        #pragma unroll
        for (int i = 0; i < 16; ++i) o2[i] = 0ull;
    }

    float lsum = 0.f;
    for (int j = 0; j < SS; ++j) {
        const u64* kj = K2 + j * 32 + half * 16;
        u64 a0 = 0ull, a1 = 0ull;
        #pragma unroll
        for (int d = 0; d < 16; d += 2) {
            a0 = ffma2(qr2[d],     kj[d],     a0);
            a1 = ffma2(qr2[d + 1], kj[d + 1], a1);
        }
        float x0, x1, y0, y1;
        unpack2(a0, x0, x1); unpack2(a1, y0, y1);
        float part = (x0 + x1) + (y0 + y1);
        float s = part + __shfl_xor_sync(0xffffffffu, part, 16);
        float p = exp2_fast(s - SOFT_OFF);
        lsum += p;
        u64 p2 = pack2(p);
        const u64* vj = V2 + j * 32 + half * 16;
        #pragma unroll
        for (int d = 0; d < 16; ++d)
            o2[d] = ffma2(p2, vj[d], o2[d]);
    }

    const float inv = 1.f / lsum;
    float* op = cat + (size_t)(nt * SS + q) * DM + h * DH + half * 32;
    #pragma unroll
    for (int i = 0; i < 8; ++i) {
        float a0, a1, b0, b1;
        unpack2(o2[i*2], a0, a1);
        unpack2(o2[i*2+1], b0, b1);
        float4 wv;
        wv.x = tf32r(a0 * inv); wv.y = tf32r(a1 * inv);
        wv.z = tf32r(b0 * inv); wv.w = tf32r(b1 * inv);
        *(float4*)(op + i * 4) = wv;
    }
}

// ============================================================================
// Temporal attention: one CTA per (n, s), 128 threads. Branch-free exp2.
// ============================================================================
__global__ void temporal_attn(const float* __restrict__ qkv, float* __restrict__ cat)
{
    extern __shared__ __align__(16) float sm[];
    float* Ks = sm;                 // [16][512]
    float* Vs = sm + TF * 512;

    const int b = blockIdx.x;
    const int n = b >> 8;
    const int s = b & 255;
    const int tid = threadIdx.x;

    #pragma unroll
    for (int i = 0; i < 16; ++i) {
        int f4 = i * 128 + tid;
        int t  = f4 >> 7;
        int c4 = (f4 & 127) << 2;
        const float* src = qkv + ((size_t)(n * TF + t) * SS + s) * QKVC + c4;
        *(float4*)(Ks + t * 512 + c4) = *(const float4*)(src + 1536);
        *(float4*)(Vs + t * 512 + c4) = *(const float4*)(src + 2560);
    }
    __syncthreads();

    const int h  = tid >> 4;
    const int tq = tid & 15;
    float qr[DH], o[DH];
    const float* qp = qkv + ((size_t)(n * TF + tq) * SS + s) * QKVC + 512 + h * DH;
    #pragma unroll
    for (int d = 0; d < DH; d += 4) {
        float4 v = *(const float4*)(qp + d);
        qr[d]   = v.x * QSCALE_LOG2; qr[d+1] = v.y * QSCALE_LOG2;
        qr[d+2] = v.z * QSCALE_LOG2; qr[d+3] = v.w * QSCALE_LOG2;
        o[d] = 0.f; o[d+1] = 0.f; o[d+2] = 0.f; o[d+3] = 0.f;
    }

    float lsum = 0.f;
    #pragma unroll
    for (int j = 0; j < TF; ++j) {
        const float* kj = Ks + j * 512 + h * DH;
        float s0 = 0.f, s1 = 0.f, s2 = 0.f, s3 = 0.f;
        #pragma unroll
        for (int d = 0; d < DH; d += 4) {
            float4 kv = *(const float4*)(kj + d);
            s0 += qr[d] * kv.x; s1 += qr[d+1] * kv.y;
            s2 += qr[d+2] * kv.z; s3 += qr[d+3] * kv.w;
        }
        float sl = (s0 + s1) + (s2 + s3);
        float p = exp2_fast(sl - SOFT_OFF);
        lsum += p;
        const float* vj = Vs + j * 512 + h * DH;
        #pragma unroll
        for (int d = 0; d < DH; d += 4) {
            float4 vv = *(const float4*)(vj + d);
            o[d]   += p * vv.x; o[d+1] += p * vv.y;
            o[d+2] += p * vv.z; o[d+3] += p * vv.w;
        }
    }
    const float inv = 1.f / lsum;
    float* op = cat + ((size_t)(n * TF + tq) * SS + s) * DM + 512 + h * DH;
    #pragma unroll
    for (int d = 0; d < DH; d += 4) {
        float4 wv;
        wv.x = tf32r(o[d] * inv);   wv.y = tf32r(o[d+1] * inv);
        wv.z = tf32r(o[d+2] * inv); wv.w = tf32r(o[d+3] * inv);
        *(float4*)(op + d) = wv;
    }
}

// ============================================================================
// Launch
// ============================================================================
extern "C" void kernel_launch(void* const* d_in, const int* in_sizes, int n_in,
                              void* d_out, int out_size)
{
    const float* x     = (const float*)d_in[0];
    const float* Wqkv  = (const float*)d_in[1];
    const float* Wproj = (const float*)d_in[2];
    const float* bproj = (const float*)d_in[3];
    float* out = (float*)d_out;

    float *qkv, *cat, *WqkvT, *WprojT;
    cudaGetSymbolAddress((void**)&qkv,    g_qkv);
    cudaGetSymbolAddress((void**)&cat,    g_cat);
    cudaGetSymbolAddress((void**)&WqkvT,  g_WqkvT);
    cudaGetSymbolAddress((void**)&WprojT, g_WprojT);

    cudaFuncSetAttribute(gemm_tf32mma, cudaFuncAttributeMaxDynamicSharedMemorySize, GEMM_SMEM);

    // 0) x -> tf32 (staged in g_cat), weights -> transposed tf32
    {
        int n4 = ROWS * DM / 4;
        cvt_tf32_vec<<<n4 / 256, 256>>>((const float4*)x, (float4*)cat, n4);
        dim3 blk(32, 8);
        transpose_k<<<dim3(QKVC/32, DM/32), blk>>>(Wqkv, WqkvT, DM, QKVC);
        transpose_k<<<dim3(DM/32, DM/32), blk>>>(Wproj, WprojT, DM, DM);
    }

    // 1) qkv = x @ Wqkv
    {
        dim3 grid(QKVC/BN, ROWS/BM);   // 24 x 32
        gemm_tf32mma<<<grid, 256, GEMM_SMEM>>>(cat, WqkvT, qkv, nullptr, ROWS, QKVC, DM);
    }

    // 2) spatial attention -> cat[:, 0:512]
    {
        int smem = 2 * SS * DH * (int)sizeof(float);   // 128 KB
        cudaFuncSetAttribute(spatial_attn, cudaFuncAttributeMaxDynamicSharedMemorySize, smem);
        spatial_attn<<<NB*TF*HEADS, 512, smem>>>(qkv, cat);
    }

    // 3) temporal attention -> cat[:, 512:1024]
    {
        int smem = 2 * TF * 512 * (int)sizeof(float);  // 64 KB
        cudaFuncSetAttribute(temporal_attn, cudaFuncAttributeMaxDynamicSharedMemorySize, smem);
        temporal_attn<<<NB*SS, 128, smem>>>(qkv, cat);
    }

    // 4) out = cat @ Wproj + bproj
    {
        dim3 grid(DM/BN, ROWS/BM);     // 8 x 32
        gemm_tf32mma<<<grid, 256, GEMM_SMEM>>>(cat, WprojT, out, bproj, ROWS, DM, DM);
    }
}

// round 10
// speedup vs baseline: 3.8037x; 1.5559x over previous
#include <cuda_runtime.h>
#include <cuda_fp16.h>
#include <cstdint>

typedef unsigned long long u64;
typedef unsigned int u32;

// ---- problem constants ----
#define NB      2
#define TF      16
#define SS      256
#define DM      1024
#define ROWS    (NB*TF*SS)        // 8192
#define QKVC    (3*DM)            // 3072
#define HEADS   8
#define DH      64
#define ATT_SCALE 0.125f
#define QSCALE_LOG2 0.18033688f   // ATT_SCALE * log2(e)
#define SOFT_OFF 4.0f             // constant offset in log2 domain (cancels in softmax)

// ---- scratch (device globals: allocation-free rule) ----
__device__ float  g_qkv[(size_t)ROWS * QKVC];    // 96 MB (fp32 GEMM1 output)
__device__ __half g_xh[(size_t)ROWS * DM];       // 16 MB (x in fp16)
__device__ __half g_cath[(size_t)ROWS * DM];     // 16 MB (attn output, fp16)
__device__ __half g_WqkvT[(size_t)QKVC * DM];    // 6 MB  (Wqkv^T fp16)
__device__ __half g_WprojT[(size_t)DM * DM];     // 2 MB  (Wproj^T fp16)

// ============================================================================
// PTX helpers (arch-neutral: mma.sync / cp.async — no tcgen05)
// ============================================================================
__device__ __forceinline__ void mma16n8k16(float* c, const u32* a, const u32* b) {
    asm volatile(
        "mma.sync.aligned.m16n8k16.row.col.f32.f16.f16.f32 "
        "{%0,%1,%2,%3}, {%4,%5,%6,%7}, {%8,%9}, {%0,%1,%2,%3};"
        : "+f"(c[0]), "+f"(c[1]), "+f"(c[2]), "+f"(c[3])
        : "r"(a[0]), "r"(a[1]), "r"(a[2]), "r"(a[3]), "r"(b[0]), "r"(b[1]));
}
__device__ __forceinline__ u32 smem_u32(const void* p) {
    u32 a;
    asm("{ .reg .u64 t; cvta.to.shared.u64 t, %1; cvt.u32.u64 %0, t; }" : "=r"(a) : "l"(p));
    return a;
}
__device__ __forceinline__ void cp_async16(u32 dst, const void* src) {
    asm volatile("cp.async.ca.shared.global [%0], [%1], 16;" :: "r"(dst), "l"(src) : "memory");
}
__device__ __forceinline__ u64 ffma2(u64 a, u64 b, u64 c) {
    u64 d;
    asm("fma.rn.f32x2 %0, %1, %2, %3;" : "=l"(d) : "l"(a), "l"(b), "l"(c));
    return d;
}
__device__ __forceinline__ u64 pack2(float x) {
    u64 d;
    asm("mov.b64 %0, {%1, %2};" : "=l"(d) : "f"(x), "f"(x));
    return d;
}
__device__ __forceinline__ void unpack2(u64 v, float& lo, float& hi) {
    asm("mov.b64 {%0, %1}, %2;" : "=f"(lo), "=f"(hi) : "l"(v));
}
// 2^t via magic-number split + deg-4 poly. FMA-pipe only, no MUFU. |t| < 30.
__device__ __forceinline__ float exp2_fast(float t) {
    float z = t + 12582912.0f;
    float n = z - 12582912.0f;
    float f = t - n;
    float p = 9.6180e-3f;
    p = fmaf(p, f, 5.55041e-2f);
    p = fmaf(p, f, 2.4022650e-1f);
    p = fmaf(p, f, 6.9314718e-1f);
    p = fmaf(p, f, 1.0f);
    return __int_as_float(__float_as_int(p) + (__float_as_int(z) << 23));
}

// ============================================================================
// x (fp32) -> fp16 copy
// ============================================================================
__global__ void cvt_f16(const float4* __restrict__ in, __half2* __restrict__ out, int n4)
{
    int i = blockIdx.x * blockDim.x + threadIdx.x;
    if (i < n4) {
        float4 v = in[i];
        out[2*i]   = __floats2half2_rn(v.x, v.y);
        out[2*i+1] = __floats2half2_rn(v.z, v.w);
    }
}

// ============================================================================
// Weight transpose + fp16 convert: W [K][N] -> WT [N][K] (fp16)
// ============================================================================
__global__ void transpose_k(const float* __restrict__ W, __half* __restrict__ WT,
                            int K, int N)
{
    __shared__ float tile[32][33];
    const int bx = blockIdx.x * 32;   // N
    const int by = blockIdx.y * 32;   // K
    const int tx = threadIdx.x, ty = threadIdx.y;   // 32 x 8
    #pragma unroll
    for (int i = 0; i < 32; i += 8)
        tile[ty + i][tx] = W[(size_t)(by + ty + i) * N + bx + tx];
    __syncthreads();
    #pragma unroll
    for (int i = 0; i < 32; i += 8)
        WT[(size_t)(bx + ty + i) * K + by + tx] = __float2half_rn(tile[tx][ty + i]);
}

// ============================================================================
// fp16 mma.sync GEMM (m16n8k16, fp32 accum), cp.async 4-stage, tile 256x128x32.
// SMEM rows: 32 half (64B) + 16B pad = 20 u32 stride -> conflict-free frags.
// 8 warps as 4x2 of 64x64 warp tiles; 4x8 m16n8k16 x 2 k-chunks per tile-k.
// One __syncthreads per iteration (4-stage ring makes the 2nd barrier dead).
// ============================================================================
#define BM 256
#define BN 128
#define BKH 32            // K per stage, in halves
#define KS32 20           // u32 stride per row (16 data + 4 pad)
#define STG 4
#define GEMM_SMEM (STG*(BM+BN)*KS32*4)   // 122880 B

__global__ void __launch_bounds__(256, 1) gemm_f16mma(
    const __half* __restrict__ A, const __half* __restrict__ BT,
    float* __restrict__ C, const float* __restrict__ bias,
    int M, int N, int K)
{
    extern __shared__ __align__(16) u32 dsm[];
    u32* As = dsm;                         // [STG][BM][KS32]
    u32* Bs = dsm + STG * BM * KS32;       // [STG][BN][KS32]

    const int tid = threadIdx.x;
    const int wid = tid >> 5;
    const int lid = tid & 31;
    const int g   = lid >> 2;
    const int tig = lid & 3;
    const int wm  = (wid >> 1) * 64;       // 0,64,128,192
    const int wn  = (wid & 1) * 64;        // 0,64
    const int bm = blockIdx.y * BM;
    const int bn = blockIdx.x * BN;
    const int pr = tid >> 2;               // 0..63
    const int pc = (tid & 3) * 4;          // u32 chunk offset (16B units *4)
    const int ph = (tid & 3) * 8;          // half offset within row

    const int NT = K / BKH;                // 32

    #define ISSUE_STAGE(t) do {                                              \
        int st_ = (t) % STG; int k0_ = (t) * BKH;                            \
        _Pragma("unroll")                                                    \
        for (int i_ = 0; i_ < 4; ++i_) {                                     \
            int m_ = i_ * 64 + pr;                                           \
            cp_async16(smem_u32(&As[(st_*BM + m_)*KS32 + pc]),               \
                       A + (size_t)(bm + m_) * K + k0_ + ph);                \
        }                                                                    \
        _Pragma("unroll")                                                    \
        for (int i_ = 0; i_ < 2; ++i_) {                                     \
            int m_ = i_ * 64 + pr;                                           \
            cp_async16(smem_u32(&Bs[(st_*BN + m_)*KS32 + pc]),               \
                       BT + (size_t)(bn + m_) * K + k0_ + ph);               \
        }                                                                    \
        asm volatile("cp.async.commit_group;" ::: "memory");                 \
    } while (0)

    ISSUE_STAGE(0);
    ISSUE_STAGE(1);

    float acc[4][8][4];
    #pragma unroll
    for (int mt = 0; mt < 4; ++mt)
        #pragma unroll
        for (int nt = 0; nt < 8; ++nt)
            #pragma unroll
            for (int i = 0; i < 4; ++i) acc[mt][nt][i] = 0.f;

    for (int t = 0; t < NT; ++t) {
        if (t < NT - 2) asm volatile("cp.async.wait_group 1;" ::: "memory");
        else            asm volatile("cp.async.wait_group 0;" ::: "memory");
        __syncthreads();
        if (t + 2 < NT) ISSUE_STAGE(t + 2);

        const int st = t % STG;
        #pragma unroll
        for (int ck = 0; ck < 2; ++ck) {
            const int kc = ck * 8 + tig;     // u32 index: ck*16 halves + 2*tig
            u32 af[4][4], bf[8][2];
            #pragma unroll
            for (int mt = 0; mt < 4; ++mt) {
                const int r = wm + mt * 16 + g;
                af[mt][0] = As[(st*BM + r    )*KS32 + kc];
                af[mt][1] = As[(st*BM + r + 8)*KS32 + kc];
                af[mt][2] = As[(st*BM + r    )*KS32 + kc + 4];
                af[mt][3] = As[(st*BM + r + 8)*KS32 + kc + 4];
            }
            #pragma unroll
            for (int nt = 0; nt < 8; ++nt) {
                const int n = wn + nt * 8 + g;
                bf[nt][0] = Bs[(st*BN + n)*KS32 + kc];
                bf[nt][1] = Bs[(st*BN + n)*KS32 + kc + 4];
            }
            #pragma unroll
            for (int mt = 0; mt < 4; ++mt)
                #pragma unroll
                for (int nt = 0; nt < 8; ++nt)
                    mma16n8k16(acc[mt][nt], af[mt], bf[nt]);
        }
    }

    #pragma unroll
    for (int mt = 0; mt < 4; ++mt) {
        const int r0 = bm + wm + mt * 16 + g;
        #pragma unroll
        for (int nt = 0; nt < 8; ++nt) {
            const int c0 = bn + wn + nt * 8 + 2 * tig;
            float2 v0, v1;
            v0.x = acc[mt][nt][0]; v0.y = acc[mt][nt][1];
            v1.x = acc[mt][nt][2]; v1.y = acc[mt][nt][3];
            if (bias) {
                float2 b2 = *(const float2*)(bias + c0);
                v0.x += b2.x; v0.y += b2.y;
                v1.x += b2.x; v1.y += b2.y;
            }
            *(float2*)(C + (size_t)r0 * N + c0)       = v0;
            *(float2*)(C + (size_t)(r0 + 8) * N + c0) = v1;
        }
    }
}

// ============================================================================
// Spatial attention: one CTA per (frame, head), 512 threads, FFMA2 + fast exp2,
// branch-free softmax. Output fp16 into g_cath[:, 0:512].
// ============================================================================
__global__ void __launch_bounds__(512) spatial_attn(
    const float* __restrict__ qkv, __half* __restrict__ cath)
{
    extern __shared__ __align__(16) char smraw[];
    u64* K2 = (u64*)smraw;              // [256][32] f32x2
    u64* V2 = K2 + SS * 32;
    float4* Kf = (float4*)K2;
    float4* Vf = (float4*)V2;

    const int b  = blockIdx.x;
    const int h  = b & 7;
    const int nt = b >> 3;
    const float* base = qkv + (size_t)nt * SS * QKVC;
    const int tid = threadIdx.x;        // 512

    #pragma unroll
    for (int i = 0; i < 16; ++i) {
        int idx = i * 512 + tid;
        int which = idx >> 12;          // 0=K, 1=V
        int r = idx & 4095;
        int row = r >> 4;
        int c = r & 15;
        const float4* src = (const float4*)(base + (size_t)row * QKVC + h * DH
                                            + c * 4 + (which ? 2048 : 1024));
        (which ? Vf : Kf)[row * 16 + c] = *src;
    }
    __syncthreads();

    const int w = tid >> 5;
    const int l = tid & 31;
    const int q = w * 16 + (l & 15);    // query 0..255
    const int half = l >> 4;            // dim half

    u64 qr2[16], o2[16];
    {
        const float* qp = base + (size_t)q * QKVC + h * DH + half * 32;
        #pragma unroll
        for (int i = 0; i < 8; ++i) {
            float4 v = *(const float4*)(qp + i * 4);
            float2 a, b2;
            a.x = v.x * QSCALE_LOG2; a.y = v.y * QSCALE_LOG2;
            b2.x = v.z * QSCALE_LOG2; b2.y = v.w * QSCALE_LOG2;
            qr2[i*2]   = *(u64*)&a;
            qr2[i*2+1] = *(u64*)&b2;
        }
        #pragma unroll
        for (int i = 0; i < 16; ++i) o2[i] = 0ull;
    }

    float lsum = 0.f;
    for (int j = 0; j < SS; ++j) {
        const u64* kj = K2 + j * 32 + half * 16;
        u64 a0 = 0ull, a1 = 0ull;
        #pragma unroll
        for (int d = 0; d < 16; d += 2) {
            a0 = ffma2(qr2[d],     kj[d],     a0);
            a1 = ffma2(qr2[d + 1], kj[d + 1], a1);
        }
        float x0, x1, y0, y1;
        unpack2(a0, x0, x1); unpack2(a1, y0, y1);
        float part = (x0 + x1) + (y0 + y1);
        float s = part + __shfl_xor_sync(0xffffffffu, part, 16);
        float p = exp2_fast(s - SOFT_OFF);
        lsum += p;
        u64 p2 = pack2(p);
        const u64* vj = V2 + j * 32 + half * 16;
        #pragma unroll
        for (int d = 0; d < 16; ++d)
            o2[d] = ffma2(p2, vj[d], o2[d]);
    }

    const float inv = 1.f / lsum;
    __half2* op = (__half2*)(cath + (size_t)(nt * SS + q) * DM + h * DH + half * 32);
    #pragma unroll
    for (int i = 0; i < 8; ++i) {
        float a0, a1, b0, b1;
        unpack2(o2[i*2], a0, a1);
        unpack2(o2[i*2+1], b0, b1);
        op[i*2]   = __floats2half2_rn(a0 * inv, a1 * inv);
        op[i*2+1] = __floats2half2_rn(b0 * inv, b1 * inv);
    }
}

// ============================================================================
// Temporal attention: one CTA per (n, s), 128 threads. Output fp16.
// ============================================================================
__global__ void temporal_attn(const float* __restrict__ qkv, __half* __restrict__ cath)
{
    extern __shared__ __align__(16) float sm[];
    float* Ks = sm;                 // [16][512]
    float* Vs = sm + TF * 512;

    const int b = blockIdx.x;
    const int n = b >> 8;
    const int s = b & 255;
    const int tid = threadIdx.x;

    #pragma unroll
    for (int i = 0; i < 16; ++i) {
        int f4 = i * 128 + tid;
        int t  = f4 >> 7;
        int c4 = (f4 & 127) << 2;
        const float* src = qkv + ((size_t)(n * TF + t) * SS + s) * QKVC + c4;
        *(float4*)(Ks + t * 512 + c4) = *(const float4*)(src + 1536);
        *(float4*)(Vs + t * 512 + c4) = *(const float4*)(src + 2560);
    }
    __syncthreads();

    const int h  = tid >> 4;
    const int tq = tid & 15;
    float qr[DH], o[DH];
    const float* qp = qkv + ((size_t)(n * TF + tq) * SS + s) * QKVC + 512 + h * DH;
    #pragma unroll
    for (int d = 0; d < DH; d += 4) {
        float4 v = *(const float4*)(qp + d);
        qr[d]   = v.x * QSCALE_LOG2; qr[d+1] = v.y * QSCALE_LOG2;
        qr[d+2] = v.z * QSCALE_LOG2; qr[d+3] = v.w * QSCALE_LOG2;
        o[d] = 0.f; o[d+1] = 0.f; o[d+2] = 0.f; o[d+3] = 0.f;
    }

    float lsum = 0.f;
    #pragma unroll
    for (int j = 0; j < TF; ++j) {
        const float* kj = Ks + j * 512 + h * DH;
        float s0 = 0.f, s1 = 0.f, s2 = 0.f, s3 = 0.f;
        #pragma unroll
        for (int d = 0; d < DH; d += 4) {
            float4 kv = *(const float4*)(kj + d);
            s0 += qr[d] * kv.x; s1 += qr[d+1] * kv.y;
            s2 += qr[d+2] * kv.z; s3 += qr[d+3] * kv.w;
        }
        float sl = (s0 + s1) + (s2 + s3);
        float p = exp2_fast(sl - SOFT_OFF);
        lsum += p;
        const float* vj = Vs + j * 512 + h * DH;
        #pragma unroll
        for (int d = 0; d < DH; d += 4) {
            float4 vv = *(const float4*)(vj + d);
            o[d]   += p * vv.x; o[d+1] += p * vv.y;
            o[d+2] += p * vv.z; o[d+3] += p * vv.w;
        }
    }
    const float inv = 1.f / lsum;
    __half2* op = (__half2*)(cath + ((size_t)(n * TF + tq) * SS + s) * DM + 512 + h * DH);
    #pragma unroll
    for (int d = 0; d < DH; d += 4) {
        op[d/2]     = __floats2half2_rn(o[d] * inv,   o[d+1] * inv);
        op[d/2 + 1] = __floats2half2_rn(o[d+2] * inv, o[d+3] * inv);
    }
}

// ============================================================================
// Launch
// ============================================================================
extern "C" void kernel_launch(void* const* d_in, const int* in_sizes, int n_in,
                              void* d_out, int out_size)
{
    const float* x     = (const float*)d_in[0];
    const float* Wqkv  = (const float*)d_in[1];
    const float* Wproj = (const float*)d_in[2];
    const float* bproj = (const float*)d_in[3];
    float* out = (float*)d_out;

    float *qkv;
    __half *xh, *cath, *WqkvT, *WprojT;
    cudaGetSymbolAddress((void**)&qkv,    g_qkv);
    cudaGetSymbolAddress((void**)&xh,     g_xh);
    cudaGetSymbolAddress((void**)&cath,   g_cath);
    cudaGetSymbolAddress((void**)&WqkvT,  g_WqkvT);
    cudaGetSymbolAddress((void**)&WprojT, g_WprojT);

    cudaFuncSetAttribute(gemm_f16mma, cudaFuncAttributeMaxDynamicSharedMemorySize, GEMM_SMEM);

    // 0) x -> fp16, weights -> transposed fp16
    {
        int n4 = ROWS * DM / 4;
        cvt_f16<<<n4 / 256, 256>>>((const float4*)x, (__half2*)xh, n4);
        dim3 blk(32, 8);
        transpose_k<<<dim3(QKVC/32, DM/32), blk>>>(Wqkv, WqkvT, DM, QKVC);
        transpose_k<<<dim3(DM/32, DM/32), blk>>>(Wproj, WprojT, DM, DM);
    }

    // 1) qkv = x @ Wqkv   (fp16 mma, fp32 accum/out)
    {
        dim3 grid(QKVC/BN, ROWS/BM);   // 24 x 32
        gemm_f16mma<<<grid, 256, GEMM_SMEM>>>(xh, WqkvT, qkv, nullptr, ROWS, QKVC, DM);
    }

    // 2) spatial attention -> cath[:, 0:512]
    {
        int smem = 2 * SS * DH * (int)sizeof(float);   // 128 KB
        cudaFuncSetAttribute(spatial_attn, cudaFuncAttributeMaxDynamicSharedMemorySize, smem);
        spatial_attn<<<NB*TF*HEADS, 512, smem>>>(qkv, cath);
    }

    // 3) temporal attention -> cath[:, 512:1024]
    {
        int smem = 2 * TF * 512 * (int)sizeof(float);  // 64 KB
        cudaFuncSetAttribute(temporal_attn, cudaFuncAttributeMaxDynamicSharedMemorySize, smem);
        temporal_attn<<<NB*SS, 128, smem>>>(qkv, cath);
    }

    // 4) out = cath @ Wproj + bproj
    {
        dim3 grid(DM/BN, ROWS/BM);     // 8 x 32
        gemm_f16mma<<<grid, 256, GEMM_SMEM>>>(cath, WprojT, out, bproj, ROWS, DM, DM);
    }
}

// round 12
// speedup vs baseline: 3.9207x; 1.0308x over previous
#include <cuda_runtime.h>
#include <cuda_fp16.h>
#include <cstdint>

typedef unsigned long long u64;
typedef unsigned int u32;

// ---- problem constants ----
#define NB      2
#define TF      16
#define SS      256
#define DM      1024
#define ROWS    (NB*TF*SS)        // 8192
#define QKVC    (3*DM)            // 3072
#define HEADS   8
#define DH      64
#define ATT_SCALE 0.125f
#define QSCALE_LOG2 0.18033688f   // ATT_SCALE * log2(e)
#define SOFT_OFF 4.0f             // constant offset in log2 domain (cancels in softmax)

// ---- scratch (device globals: allocation-free rule) ----
__device__ float  g_qkv[(size_t)ROWS * QKVC];    // 96 MB (fp32 GEMM1 output)
__device__ __half g_xh[(size_t)ROWS * DM];       // 16 MB (x in fp16)
__device__ __half g_cath[(size_t)ROWS * DM];     // 16 MB (attn output, fp16)
__device__ __half g_WqkvT[(size_t)QKVC * DM];    // 6 MB  (Wqkv^T fp16)
__device__ __half g_WprojT[(size_t)DM * DM];     // 2 MB  (Wproj^T fp16)

// ============================================================================
// PTX helpers (arch-neutral: mma.sync / cp.async / ldmatrix — no tcgen05)
// ============================================================================
__device__ __forceinline__ void mma16n8k16(float* c, const u32* a, const u32* b) {
    asm volatile(
        "mma.sync.aligned.m16n8k16.row.col.f32.f16.f16.f32 "
        "{%0,%1,%2,%3}, {%4,%5,%6,%7}, {%8,%9}, {%0,%1,%2,%3};"
        : "+f"(c[0]), "+f"(c[1]), "+f"(c[2]), "+f"(c[3])
        : "r"(a[0]), "r"(a[1]), "r"(a[2]), "r"(a[3]), "r"(b[0]), "r"(b[1]));
}
__device__ __forceinline__ u32 smem_u32(const void* p) {
    u32 a;
    asm("{ .reg .u64 t; cvta.to.shared.u64 t, %1; cvt.u32.u64 %0, t; }" : "=r"(a) : "l"(p));
    return a;
}
__device__ __forceinline__ void cp_async16(u32 dst, const void* src) {
    asm volatile("cp.async.ca.shared.global [%0], [%1], 16;" :: "r"(dst), "l"(src) : "memory");
}
__device__ __forceinline__ void ldmx4(u32* r, u32 addr) {
    asm volatile("ldmatrix.sync.aligned.m8n8.x4.shared.b16 {%0,%1,%2,%3}, [%4];"
                 : "=r"(r[0]), "=r"(r[1]), "=r"(r[2]), "=r"(r[3]) : "r"(addr));
}
__device__ __forceinline__ u64 ffma2(u64 a, u64 b, u64 c) {
    u64 d;
    asm("fma.rn.f32x2 %0, %1, %2, %3;" : "=l"(d) : "l"(a), "l"(b), "l"(c));
    return d;
}
__device__ __forceinline__ u64 pack2(float x) {
    u64 d;
    asm("mov.b64 %0, {%1, %2};" : "=l"(d) : "f"(x), "f"(x));
    return d;
}
__device__ __forceinline__ void unpack2(u64 v, float& lo, float& hi) {
    asm("mov.b64 {%0, %1}, %2;" : "=f"(lo), "=f"(hi) : "l"(v));
}
// 2^t via magic-number split + deg-4 poly. FMA-pipe only, no MUFU. |t| < 30.
__device__ __forceinline__ float exp2_fast(float t) {
    float z = t + 12582912.0f;
    float n = z - 12582912.0f;
    float f = t - n;
    float p = 9.6180e-3f;
    p = fmaf(p, f, 5.55041e-2f);
    p = fmaf(p, f, 2.4022650e-1f);
    p = fmaf(p, f, 6.9314718e-1f);
    p = fmaf(p, f, 1.0f);
    return __int_as_float(__float_as_int(p) + (__float_as_int(z) << 23));
}

// ============================================================================
// x (fp32) -> fp16 copy
// ============================================================================
__global__ void cvt_f16(const float4* __restrict__ in, __half2* __restrict__ out, int n4)
{
    int i = blockIdx.x * blockDim.x + threadIdx.x;
    if (i < n4) {
        float4 v = in[i];
        out[2*i]   = __floats2half2_rn(v.x, v.y);
        out[2*i+1] = __floats2half2_rn(v.z, v.w);
    }
}

// ============================================================================
// Weight transpose + fp16 convert: W [K][N] -> WT [N][K] (fp16)
// ============================================================================
__global__ void transpose_k(const float* __restrict__ W, __half* __restrict__ WT,
                            int K, int N)
{
    __shared__ float tile[32][33];
    const int bx = blockIdx.x * 32;   // N
    const int by = blockIdx.y * 32;   // K
    const int tx = threadIdx.x, ty = threadIdx.y;   // 32 x 8
    #pragma unroll
    for (int i = 0; i < 32; i += 8)
        tile[ty + i][tx] = W[(size_t)(by + ty + i) * N + bx + tx];
    __syncthreads();
    #pragma unroll
    for (int i = 0; i < 32; i += 8)
        WT[(size_t)(bx + ty + i) * K + by + tx] = __float2half_rn(tile[tx][ty + i]);
}

// ============================================================================
// fp16 mma.sync GEMM (m16n8k16, fp32 accum), cp.async 4-stage, tile 256x128x32.
// Fragment loads via ldmatrix.x4 (16 instr/tile-k vs 64 scalar LDS).
// SMEM rows: 32 half (64B) + 16B pad = 20 u32 stride; the 8 tile rows hit
// banks {0,20,8,28,16,4,24,12}x4 -> full 32-bank permutation, conflict-free.
// ============================================================================
#define BM 256
#define BN 128
#define BKH 32            // K per stage, in halves
#define KS32 20           // u32 stride per row (16 data + 4 pad)
#define STG 4
#define GEMM_SMEM (STG*(BM+BN)*KS32*4)   // 122880 B

__global__ void __launch_bounds__(256, 1) gemm_f16mma(
    const __half* __restrict__ A, const __half* __restrict__ BT,
    float* __restrict__ C, const float* __restrict__ bias,
    int M, int N, int K)
{
    extern __shared__ __align__(16) u32 dsm[];
    u32* As = dsm;                         // [STG][BM][KS32]
    u32* Bs = dsm + STG * BM * KS32;       // [STG][BN][KS32]

    const int tid = threadIdx.x;
    const int wid = tid >> 5;
    const int lid = tid & 31;
    const int g   = lid >> 2;
    const int tig = lid & 3;
    const int wm  = (wid >> 1) * 64;       // 0,64,128,192
    const int wn  = (wid & 1) * 64;        // 0,64
    const int bm = blockIdx.y * BM;
    const int bn = blockIdx.x * BN;
    const int pr = tid >> 2;               // 0..63
    const int pc = (tid & 3) * 4;          // u32 chunk offset
    const int ph = (tid & 3) * 8;          // half offset within row

    // ldmatrix per-lane addressing: lane = 8*tile + row
    const int lrow = lid & 7;
    const int lt   = lid >> 3;             // tile index 0..3
    const u32 smA = smem_u32(As);
    const u32 smB = smem_u32(Bs);
    // A x4 per mt: tiles (r0-7,k0-7),(r8-15,k0-7),(r0-7,k8-15),(r8-15,k8-15)
    u32 aoff[4], boff[4];
    #pragma unroll
    for (int mt = 0; mt < 4; ++mt)
        aoff[mt] = (u32)(((wm + mt*16 + lrow + (lt & 1)*8) * KS32 + (lt >> 1)*4) * 4);
    // B x4 per pair p: tiles (n0-7,k0-7),(n0-7,k8-15),(n8-15,k0-7),(n8-15,k8-15)
    #pragma unroll
    for (int p = 0; p < 4; ++p)
        boff[p] = (u32)(((wn + p*16 + (lt >> 1)*8 + lrow) * KS32 + (lt & 1)*4) * 4);

    const int NT = K / BKH;                // 32

    #define ISSUE_STAGE(t) do {                                              \
        int st_ = (t) % STG; int k0_ = (t) * BKH;                            \
        _Pragma("unroll")                                                    \
        for (int i_ = 0; i_ < 4; ++i_) {                                     \
            int m_ = i_ * 64 + pr;                                           \
            cp_async16(smem_u32(&As[(st_*BM + m_)*KS32 + pc]),               \
                       A + (size_t)(bm + m_) * K + k0_ + ph);                \
        }                                                                    \
        _Pragma("unroll")                                                    \
        for (int i_ = 0; i_ < 2; ++i_) {                                     \
            int m_ = i_ * 64 + pr;                                           \
            cp_async16(smem_u32(&Bs[(st_*BN + m_)*KS32 + pc]),               \
                       BT + (size_t)(bn + m_) * K + k0_ + ph);               \
        }                                                                    \
        asm volatile("cp.async.commit_group;" ::: "memory");                 \
    } while (0)

    ISSUE_STAGE(0);
    ISSUE_STAGE(1);

    float acc[4][8][4];
    #pragma unroll
    for (int mt = 0; mt < 4; ++mt)
        #pragma unroll
        for (int nt = 0; nt < 8; ++nt)
            #pragma unroll
            for (int i = 0; i < 4; ++i) acc[mt][nt][i] = 0.f;

    for (int t = 0; t < NT; ++t) {
        if (t < NT - 2) asm volatile("cp.async.wait_group 1;" ::: "memory");
        else            asm volatile("cp.async.wait_group 0;" ::: "memory");
        __syncthreads();
        if (t + 2 < NT) ISSUE_STAGE(t + 2);

        const int st = t % STG;
        const u32 stA = smA + (u32)(st * BM * KS32 * 4);
        const u32 stB = smB + (u32)(st * BN * KS32 * 4);
        #pragma unroll
        for (int ck = 0; ck < 2; ++ck) {
            const u32 cko = (u32)(ck * 8 * 4);
            u32 af[4][4], bf[8][2];
            #pragma unroll
            for (int mt = 0; mt < 4; ++mt)
                ldmx4(af[mt], stA + aoff[mt] + cko);
            #pragma unroll
            for (int p = 0; p < 4; ++p) {
                u32 r[4];
                ldmx4(r, stB + boff[p] + cko);
                bf[2*p][0]   = r[0]; bf[2*p][1]   = r[1];
                bf[2*p+1][0] = r[2]; bf[2*p+1][1] = r[3];
            }
            #pragma unroll
            for (int mt = 0; mt < 4; ++mt)
                #pragma unroll
                for (int nt = 0; nt < 8; ++nt)
                    mma16n8k16(acc[mt][nt], af[mt], bf[nt]);
        }
    }

    #pragma unroll
    for (int mt = 0; mt < 4; ++mt) {
        const int r0 = bm + wm + mt * 16 + g;
        #pragma unroll
        for (int nt = 0; nt < 8; ++nt) {
            const int c0 = bn + wn + nt * 8 + 2 * tig;
            float2 v0, v1;
            v0.x = acc[mt][nt][0]; v0.y = acc[mt][nt][1];
            v1.x = acc[mt][nt][2]; v1.y = acc[mt][nt][3];
            if (bias) {
                float2 b2 = *(const float2*)(bias + c0);
                v0.x += b2.x; v0.y += b2.y;
                v1.x += b2.x; v1.y += b2.y;
            }
            *(float2*)(C + (size_t)r0 * N + c0)       = v0;
            *(float2*)(C + (size_t)(r0 + 8) * N + c0) = v1;
        }
    }
}

// ============================================================================
// Spatial attention: one CTA per (frame, head), 512 threads, FFMA2 + fast exp2,
// branch-free softmax. Output fp16 into g_cath[:, 0:512].
// ============================================================================
__global__ void __launch_bounds__(512) spatial_attn(
    const float* __restrict__ qkv, __half* __restrict__ cath)
{
    extern __shared__ __align__(16) char smraw[];
    u64* K2 = (u64*)smraw;              // [256][32] f32x2
    u64* V2 = K2 + SS * 32;
    float4* Kf = (float4*)K2;
    float4* Vf = (float4*)V2;

    const int b  = blockIdx.x;
    const int h  = b & 7;
    const int nt = b >> 3;
    const float* base = qkv + (size_t)nt * SS * QKVC;
    const int tid = threadIdx.x;        // 512

    #pragma unroll
    for (int i = 0; i < 16; ++i) {
        int idx = i * 512 + tid;
        int which = idx >> 12;          // 0=K, 1=V
        int r = idx & 4095;
        int row = r >> 4;
        int c = r & 15;
        const float4* src = (const float4*)(base + (size_t)row * QKVC + h * DH
                                            + c * 4 + (which ? 2048 : 1024));
        (which ? Vf : Kf)[row * 16 + c] = *src;
    }
    __syncthreads();

    const int w = tid >> 5;
    const int l = tid & 31;
    const int q = w * 16 + (l & 15);    // query 0..255
    const int half = l >> 4;            // dim half

    u64 qr2[16], o2[16];
    {
        const float* qp = base + (size_t)q * QKVC + h * DH + half * 32;
        #pragma unroll
        for (int i = 0; i < 8; ++i) {
            float4 v = *(const float4*)(qp + i * 4);
            float2 a, b2;
            a.x = v.x * QSCALE_LOG2; a.y = v.y * QSCALE_LOG2;
            b2.x = v.z * QSCALE_LOG2; b2.y = v.w * QSCALE_LOG2;
            qr2[i*2]   = *(u64*)&a;
            qr2[i*2+1] = *(u64*)&b2;
        }
        #pragma unroll
        for (int i = 0; i < 16; ++i) o2[i] = 0ull;
    }

    float lsum = 0.f;
    for (int j = 0; j < SS; ++j) {
        const u64* kj = K2 + j * 32 + half * 16;
        u64 a0 = 0ull, a1 = 0ull;
        #pragma unroll
        for (int d = 0; d < 16; d += 2) {
            a0 = ffma2(qr2[d],     kj[d],     a0);
            a1 = ffma2(qr2[d + 1], kj[d + 1], a1);
        }
        float x0, x1, y0, y1;
        unpack2(a0, x0, x1); unpack2(a1, y0, y1);
        float part = (x0 + x1) + (y0 + y1);
        float s = part + __shfl_xor_sync(0xffffffffu, part, 16);
        float p = exp2_fast(s - SOFT_OFF);
        lsum += p;
        u64 p2 = pack2(p);
        const u64* vj = V2 + j * 32 + half * 16;
        #pragma unroll
        for (int d = 0; d < 16; ++d)
            o2[d] = ffma2(p2, vj[d], o2[d]);
    }

    const float inv = 1.f / lsum;
    __half2* op = (__half2*)(cath + (size_t)(nt * SS + q) * DM + h * DH + half * 32);
    #pragma unroll
    for (int i = 0; i < 8; ++i) {
        float a0, a1, b0, b1;
        unpack2(o2[i*2], a0, a1);
        unpack2(o2[i*2+1], b0, b1);
        op[i*2]   = __floats2half2_rn(a0 * inv, a1 * inv);
        op[i*2+1] = __floats2half2_rn(b0 * inv, b1 * inv);
    }
}

// ============================================================================
// Temporal attention: one CTA per (n, s), 128 threads. Output fp16.
// ============================================================================
__global__ void temporal_attn(const float* __restrict__ qkv, __half* __restrict__ cath)
{
    extern __shared__ __align__(16) float sm[];
    float* Ks = sm;                 // [16][512]
    float* Vs = sm + TF * 512;

    const int b = blockIdx.x;
    const int n = b >> 8;
    const int s = b & 255;
    const int tid = threadIdx.x;

    #pragma unroll
    for (int i = 0; i < 16; ++i) {
        int f4 = i * 128 + tid;
        int t  = f4 >> 7;
        int c4 = (f4 & 127) << 2;
        const float* src = qkv + ((size_t)(n * TF + t) * SS + s) * QKVC + c4;
        *(float4*)(Ks + t * 512 + c4) = *(const float4*)(src + 1536);
        *(float4*)(Vs + t * 512 + c4) = *(const float4*)(src + 2560);
    }
    __syncthreads();

    const int h  = tid >> 4;
    const int tq = tid & 15;
    float qr[DH], o[DH];
    const float* qp = qkv + ((size_t)(n * TF + tq) * SS + s) * QKVC + 512 + h * DH;
    #pragma unroll
    for (int d = 0; d < DH; d += 4) {
        float4 v = *(const float4*)(qp + d);
        qr[d]   = v.x * QSCALE_LOG2; qr[d+1] = v.y * QSCALE_LOG2;
        qr[d+2] = v.z * QSCALE_LOG2; qr[d+3] = v.w * QSCALE_LOG2;
        o[d] = 0.f; o[d+1] = 0.f; o[d+2] = 0.f; o[d+3] = 0.f;
    }

    float lsum = 0.f;
    #pragma unroll
    for (int j = 0; j < TF; ++j) {
        const float* kj = Ks + j * 512 + h * DH;
        float s0 = 0.f, s1 = 0.f, s2 = 0.f, s3 = 0.f;
        #pragma unroll
        for (int d = 0; d < DH; d += 4) {
            float4 kv = *(const float4*)(kj + d);
            s0 += qr[d] * kv.x; s1 += qr[d+1] * kv.y;
            s2 += qr[d+2] * kv.z; s3 += qr[d+3] * kv.w;
        }
        float sl = (s0 + s1) + (s2 + s3);
        float p = exp2_fast(sl - SOFT_OFF);
        lsum += p;
        const float* vj = Vs + j * 512 + h * DH;
        #pragma unroll
        for (int d = 0; d < DH; d += 4) {
            float4 vv = *(const float4*)(vj + d);
            o[d]   += p * vv.x; o[d+1] += p * vv.y;
            o[d+2] += p * vv.z; o[d+3] += p * vv.w;
        }
    }
    const float inv = 1.f / lsum;
    __half2* op = (__half2*)(cath + ((size_t)(n * TF + tq) * SS + s) * DM + 512 + h * DH);
    #pragma unroll
    for (int d = 0; d < DH; d += 4) {
        op[d/2]     = __floats2half2_rn(o[d] * inv,   o[d+1] * inv);
        op[d/2 + 1] = __floats2half2_rn(o[d+2] * inv, o[d+3] * inv);
    }
}

// ============================================================================
// Launch
// ============================================================================
extern "C" void kernel_launch(void* const* d_in, const int* in_sizes, int n_in,
                              void* d_out, int out_size)
{
    const float* x     = (const float*)d_in[0];
    const float* Wqkv  = (const float*)d_in[1];
    const float* Wproj = (const float*)d_in[2];
    const float* bproj = (const float*)d_in[3];
    float* out = (float*)d_out;

    float *qkv;
    __half *xh, *cath, *WqkvT, *WprojT;
    cudaGetSymbolAddress((void**)&qkv,    g_qkv);
    cudaGetSymbolAddress((void**)&xh,     g_xh);
    cudaGetSymbolAddress((void**)&cath,   g_cath);
    cudaGetSymbolAddress((void**)&WqkvT,  g_WqkvT);
    cudaGetSymbolAddress((void**)&WprojT, g_WprojT);

    cudaFuncSetAttribute(gemm_f16mma, cudaFuncAttributeMaxDynamicSharedMemorySize, GEMM_SMEM);

    // 0) x -> fp16, weights -> transposed fp16
    {
        int n4 = ROWS * DM / 4;
        cvt_f16<<<n4 / 256, 256>>>((const float4*)x, (__half2*)xh, n4);
        dim3 blk(32, 8);
        transpose_k<<<dim3(QKVC/32, DM/32), blk>>>(Wqkv, WqkvT, DM, QKVC);
        transpose_k<<<dim3(DM/32, DM/32), blk>>>(Wproj, WprojT, DM, DM);
    }

    // 1) qkv = x @ Wqkv   (fp16 mma, fp32 accum/out)
    {
        dim3 grid(QKVC/BN, ROWS/BM);   // 24 x 32
        gemm_f16mma<<<grid, 256, GEMM_SMEM>>>(xh, WqkvT, qkv, nullptr, ROWS, QKVC, DM);
    }

    // 2) spatial attention -> cath[:, 0:512]
    {
        int smem = 2 * SS * DH * (int)sizeof(float);   // 128 KB
        cudaFuncSetAttribute(spatial_attn, cudaFuncAttributeMaxDynamicSharedMemorySize, smem);
        spatial_attn<<<NB*TF*HEADS, 512, smem>>>(qkv, cath);
    }

    // 3) temporal attention -> cath[:, 512:1024]
    {
        int smem = 2 * TF * 512 * (int)sizeof(float);  // 64 KB
        cudaFuncSetAttribute(temporal_attn, cudaFuncAttributeMaxDynamicSharedMemorySize, smem);
        temporal_attn<<<NB*SS, 128, smem>>>(qkv, cath);
    }

    // 4) out = cath @ Wproj + bproj
    {
        dim3 grid(DM/BN, ROWS/BM);     // 8 x 32
        gemm_f16mma<<<grid, 256, GEMM_SMEM>>>(cath, WprojT, out, bproj, ROWS, DM, DM);
    }
}